// round 11
// baseline (speedup 1.0000x reference)
#include <cuda_runtime.h>
#include <cuda_bf16.h>
#include <cstdint>
#include <cstddef>

#define B_   8
#define N_   8192
#define M_   2048
#define CIN  64
#define AROW 132       // A row stride in u32 pairs (132 mod 32 = 4 -> conflict-free)
#define WROW 68        // W buf row stride in u32 (68 mod 32 = 4 -> conflict-free)

// ---- SMEM layout (bytes) ----
#define OFF_BIAS 0                         // 512 f32
#define OFF_PMAX 2048                      // 8 x 128 f32
#define OFF_A    8192                      // 256 x 132 u32 = 135168
#define OFF_W0   (OFF_A + 256 * AROW * 4)  // 143360, 128 x 68 u32 = 34816
#define OFF_W1   (OFF_W0 + 128 * WROW * 4) // 178176
#define SMEM_BYTES (OFF_W1 + 128 * WROW * 4)   // 212992

// packed weights, PAIR layout per row: u32[k] (k even) = {hi(k),hi(k+1)},
// u32[k] (k odd) = {lo(k-1),lo(k)}; n-major rows.
// W1p @0 (pitch 80), W2p @10240 (128), W3h0 @26624 (128), W3h1 @43008 (128)
#define W1P  0
#define W2P  10240
#define W3AP 26624
#define W3BP 43008
__device__ __align__(16) uint32_t g_wp[59392];
__device__ float g_featT[(size_t)B_ * N_ * CIN];   // featT[b][n][c]

__device__ __forceinline__ void bsplit(float v, __nv_bfloat16& h, __nv_bfloat16& l) {
    h = __float2bfloat16(v);
    l = __float2bfloat16(v - __bfloat162float(h));
}
__device__ __forceinline__ uint32_t pk(__nv_bfloat16 a, __nv_bfloat16 b) {
    __nv_bfloat162 t(a, b);
    return *(uint32_t*)&t;
}
// pack 4 cols -> uint4 {hi01, lo01, hi23, lo23}  (pair layout)
__device__ __forceinline__ uint4 pack4(const float* v) {
    __nv_bfloat16 h0,l0,h1,l1,h2,l2,h3,l3;
    bsplit(v[0], h0, l0); bsplit(v[1], h1, l1);
    bsplit(v[2], h2, l2); bsplit(v[3], h3, l3);
    uint4 q;
    q.x = pk(h0, h1); q.y = pk(l0, l1);
    q.z = pk(h2, h3); q.w = pk(l2, l3);
    return q;
}

__device__ __forceinline__ void mma_bf16(float c[4], const uint32_t a[4],
                                         uint32_t b0, uint32_t b1) {
    asm volatile(
        "mma.sync.aligned.m16n8k16.row.col.f32.bf16.bf16.f32 "
        "{%0,%1,%2,%3}, {%4,%5,%6,%7}, {%8,%9}, {%0,%1,%2,%3};"
        : "+f"(c[0]), "+f"(c[1]), "+f"(c[2]), "+f"(c[3])
        : "r"(a[0]), "r"(a[1]), "r"(a[2]), "r"(a[3]), "r"(b0), "r"(b1));
}
__device__ __forceinline__ void cp16(uint32_t smem_dst, const void* gsrc) {
    asm volatile("cp.async.cg.shared.global [%0], [%1], 16;"
                 :: "r"(smem_dst), "l"(gsrc) : "memory");
}
#define CP_COMMIT() asm volatile("cp.async.commit_group;" ::: "memory")
#define CP_WAIT(n)  asm volatile("cp.async.wait_group %0;" :: "n"(n) : "memory")

// m32 x n64 warp tile, 3-pass bf16. A at global k = kbase + local; W local [0, KS*16).
template<int KS>
__device__ __forceinline__ void gemm_chunk(const uint32_t* __restrict__ sA,
                                           const uint32_t* __restrict__ sW,
                                           int kbase, int r0, int n0, int lane,
                                           float C[2][8][4])
{
    const int rq = lane >> 2, kq = (lane & 3) * 2;
    #pragma unroll
    for (int ks = 0; ks < KS; ks++) {
        const int ka = kbase + ks * 16 + kq;
        const int kw = ks * 16 + kq;
        uint2 a2[2][4];
        #pragma unroll
        for (int mt = 0; mt < 2; mt++) {
            const uint32_t* pA = sA + (r0 + mt * 16 + rq) * AROW;
            a2[mt][0] = *(const uint2*)(pA + ka);
            a2[mt][1] = *(const uint2*)(pA + 8 * AROW + ka);
            a2[mt][2] = *(const uint2*)(pA + ka + 8);
            a2[mt][3] = *(const uint2*)(pA + 8 * AROW + ka + 8);
        }
        uint32_t ahi[2][4], alo[2][4];
        #pragma unroll
        for (int mt = 0; mt < 2; mt++)
            #pragma unroll
            for (int i = 0; i < 4; i++) {
                ahi[mt][i] = a2[mt][i].x;
                alo[mt][i] = a2[mt][i].y;
            }
        #pragma unroll
        for (int j = 0; j < 8; j++) {
            const uint32_t* pW = sW + (n0 + j * 8 + rq) * WROW;
            uint2 w0 = *(const uint2*)(pW + kw);
            uint2 w1 = *(const uint2*)(pW + kw + 8);
            mma_bf16(C[0][j], ahi[0], w0.x, w1.x);
            mma_bf16(C[1][j], ahi[1], w0.x, w1.x);
            mma_bf16(C[0][j], ahi[0], w0.y, w1.y);
            mma_bf16(C[1][j], ahi[1], w0.y, w1.y);
            mma_bf16(C[0][j], alo[0], w0.x, w1.x);
            mma_bf16(C[1][j], alo[1], w0.x, w1.x);
        }
    }
}

__device__ __forceinline__ void zeroC(float C[2][8][4]) {
    #pragma unroll
    for (int mt = 0; mt < 2; mt++)
        #pragma unroll
        for (int j = 0; j < 8; j++)
            #pragma unroll
            for (int x = 0; x < 4; x++) C[mt][j][x] = 0.f;
}

__device__ __forceinline__ void epi(const float C[2][8][4], const float* __restrict__ bias,
                                    int r0, int n0, int lane, uint32_t* __restrict__ sA)
{
    const int rq = lane >> 2, q2 = (lane & 3) * 2;
    #pragma unroll
    for (int mt = 0; mt < 2; mt++) {
        const int ra = r0 + mt * 16 + rq;
        #pragma unroll
        for (int j = 0; j < 8; j++) {
            const int c0 = n0 + j * 8 + q2;
            const float bb0 = bias[c0], bb1 = bias[c0 + 1];
            float v0 = fmaxf(C[mt][j][0] + bb0, 0.f);
            float v1 = fmaxf(C[mt][j][1] + bb1, 0.f);
            float v2 = fmaxf(C[mt][j][2] + bb0, 0.f);
            float v3 = fmaxf(C[mt][j][3] + bb1, 0.f);
            __nv_bfloat16 h0,l0,h1,l1;
            uint2 p;
            bsplit(v0, h0, l0); bsplit(v1, h1, l1);
            p.x = pk(h0, h1); p.y = pk(l0, l1);
            *(uint2*)(sA + ra * AROW + c0) = p;
            bsplit(v2, h0, l0); bsplit(v3, h1, l1);
            p.x = pk(h0, h1); p.y = pk(l0, l1);
            *(uint2*)(sA + (ra + 8) * AROW + c0) = p;
        }
    }
}

// ---------------- prep: pack weights to g_wp (PAIR layout) ----------------
__global__ __launch_bounds__(256) void prep_kernel(const float* __restrict__ W1,
                                                   const float* __restrict__ W2,
                                                   const float* __restrict__ W3)
{
    const int idx = blockIdx.x * 256 + threadIdx.x;
    if (idx >= 59392) return;
    const float* W; int ld, coloff, kreal, n, k;
    if (idx < 10240) {
        W = W1; ld = 128; coloff = 0; kreal = 67;
        n = idx / 80; k = idx % 80;
    } else if (idx < 26624) {
        W = W2; ld = 128; coloff = 0; kreal = 128;
        const int t = idx - 10240; n = t >> 7; k = t & 127;
    } else if (idx < 43008) {
        W = W3; ld = 256; coloff = 0; kreal = 128;
        const int t = idx - 26624; n = t >> 7; k = t & 127;
    } else {
        W = W3; ld = 256; coloff = 128; kreal = 128;
        const int t = idx - 43008; n = t >> 7; k = t & 127;
    }
    const int k0 = k & ~1;
    const float v0 = (k0     < kreal) ? W[(size_t)k0 * ld + coloff + n] : 0.f;
    const float v1 = (k0 + 1 < kreal) ? W[(size_t)(k0 + 1) * ld + coloff + n] : 0.f;
    __nv_bfloat16 h0, l0, h1, l1;
    bsplit(v0, h0, l0); bsplit(v1, h1, l1);
    g_wp[idx] = (k & 1) ? pk(l0, l1) : pk(h0, h1);
}

// ---------------- feature transpose [C][N] -> [N][C] ----------------
__global__ __launch_bounds__(256) void tr_kernel(const float* __restrict__ feat) {
    __shared__ float t[64][65];
    const int b  = blockIdx.x >> 7;
    const int n0 = (blockIdx.x & 127) << 6;
    const int tid = threadIdx.x;
    const float* fb = feat + (size_t)b * CIN * N_;
    for (int i = tid; i < 64 * 64; i += 256) {
        int c = i >> 6, nj = i & 63;
        t[c][nj] = fb[(size_t)c * N_ + n0 + nj];
    }
    __syncthreads();
    const int nj = tid >> 2, cq = (tid & 3) * 16;
    float* drow = g_featT + ((size_t)b * N_ + n0 + nj) * CIN + cq;
    #pragma unroll
    for (int q = 0; q < 16; q += 4) {
        float4 v = make_float4(t[cq + q][nj], t[cq + q + 1][nj],
                               t[cq + q + 2][nj], t[cq + q + 3][nj]);
        *(float4*)(drow + q) = v;
    }
}

// ---------------- main: 256 rows / 8 neighborhoods per CTA ----------------
__global__ __launch_bounds__(512, 1)
void ps_mma6(const float* __restrict__ xyz,
             const int* __restrict__ nbr, const int* __restrict__ anc,
             const float* __restrict__ b1, const float* __restrict__ b2,
             const float* __restrict__ b3, float* __restrict__ out)
{
    extern __shared__ char smem[];
    float* bias = (float*)(smem + OFF_BIAS);
    float* pmax = (float*)(smem + OFF_PMAX);
    uint32_t* sA = (uint32_t*)(smem + OFF_A);
    const uint32_t* wb0 = (const uint32_t*)(smem + OFF_W0);
    const uint32_t* wb1 = (const uint32_t*)(smem + OFF_W1);
    const uint32_t sbase = (uint32_t)__cvta_generic_to_shared(smem);

    const int tid = threadIdx.x, lane = tid & 31, w = tid >> 5;
    const int ct = blockIdx.x, b = ct >> 8;
    const int m0 = (ct & 255) << 3;       // 8 anchors per CTA

    // cp.async stage: 128 rows, u32 cols [kb, kb+len) of packed array -> buf
    auto stage = [&](int srcOff, int pitch, int kb, int len, int bufOff) {
        const int n16 = len >> 2;                      // 16B units per row
        const int total = 128 * n16;
        for (int q = tid; q < total; q += 512) {
            const int n = q / n16, c4 = q % n16;
            cp16(sbase + bufOff + (n * WROW + c4 * 4) * 4,
                 (const char*)g_wp + (size_t)(srcOff + n * pitch + kb + c4 * 4) * 4);
        }
        CP_COMMIT();
    };

    stage(W1P, 80, 0,  64, OFF_W0);    // grp1
    stage(W1P, 80, 64, 16, OFF_W1);    // grp2

    bias[tid] = (tid < 128) ? b1[tid] : (tid < 256) ? b2[tid - 128] : b3[tid - 256];

    // ---- gather rows [256][80]: float4 feature loads ----
    {
        const int r = tid >> 1, h = tid & 1;
        const int m = m0 + (r >> 5), k = r & 31;
        const int n = nbr[(b * M_ + m) * 32 + k];
        const float4* f4 = (const float4*)(g_featT + ((size_t)b * N_ + n) * CIN);
        uint32_t* pA = sA + r * AROW;
        if (h == 0) {
            const int a = anc[b * M_ + m];
            const float* xb = xyz + (size_t)b * N_ * 3;
            float4 blk[9];
            #pragma unroll
            for (int i = 0; i < 9; i++) blk[i] = __ldg(f4 + i);   // feats 0..35
            float v[4];
            v[0] = xb[n * 3 + 0] - xb[a * 3 + 0];
            v[1] = xb[n * 3 + 1] - xb[a * 3 + 1];
            v[2] = xb[n * 3 + 2] - xb[a * 3 + 2];
            v[3] = blk[0].x;                                      // feat0
            *(uint4*)(pA + 0) = pack4(v);
            #pragma unroll
            for (int g = 1; g <= 8; g++) {                        // cols 4g..4g+3 = feats 4g-3..4g
                v[0] = blk[g - 1].y; v[1] = blk[g - 1].z;
                v[2] = blk[g - 1].w; v[3] = blk[g].x;
                *(uint4*)(pA + 4 * g) = pack4(v);
            }
        } else {
            float4 blk[8];
            #pragma unroll
            for (int i = 0; i < 8; i++) blk[i] = __ldg(f4 + 8 + i);  // feats 32..63
            float v[4];
            #pragma unroll
            for (int g = 9; g <= 16; g++) {                       // cols 4g..4g+3 = feats 4g-3..4g
                const int f = 4 * g - 3;
                const int i0 = (f - 32) >> 2;
                v[0] = blk[i0].y; v[1] = blk[i0].z; v[2] = blk[i0].w;
                v[3] = (g < 16) ? blk[i0 + 1].x : 0.f;
                *(uint4*)(pA + 4 * g) = pack4(v);
            }
            const uint4 z = make_uint4(0, 0, 0, 0);
            *(uint4*)(pA + 68) = z;
            *(uint4*)(pA + 72) = z;
            *(uint4*)(pA + 76) = z;
        }
    }

    const int rg = w & 7;               // neighborhood / row group
    const int r0 = rg * 32;
    const int n0 = (w >> 3) * 64;       // col half
    float C[2][8][4];

    // ---- layer 1: K=80 ----
    CP_WAIT(1); __syncthreads();                       // grp1 (W1 k0-63) ready
    zeroC(C);
    gemm_chunk<4>(sA, wb0, 0, r0, n0, lane, C);
    __syncthreads();
    stage(W2P, 128, 0, 64, OFF_W0);                    // grp3
    CP_WAIT(1); __syncthreads();                       // grp2 (W1 k64-79) ready
    gemm_chunk<1>(sA, wb1, 64, r0, n0, lane, C);
    __syncthreads();
    epi(C, bias, r0, n0, lane, sA);
    stage(W2P, 128, 64, 64, OFF_W1);                   // grp4
    CP_WAIT(1); __syncthreads();                       // grp3 (W2 k0-63) ready

    // ---- layer 2: K=128 ----
    zeroC(C);
    gemm_chunk<4>(sA, wb0, 0, r0, n0, lane, C);
    __syncthreads();
    stage(W3AP, 128, 0, 64, OFF_W0);                   // grp5
    CP_WAIT(1); __syncthreads();                       // grp4 ready
    gemm_chunk<4>(sA, wb1, 64, r0, n0, lane, C);
    __syncthreads();
    epi(C, bias + 128, r0, n0, lane, sA);
    stage(W3AP, 128, 64, 64, OFF_W1);                  // grp6
    CP_WAIT(1); __syncthreads();                       // grp5 ready

    // ---- layer 3 half 0 ----
    zeroC(C);
    gemm_chunk<4>(sA, wb0, 0, r0, n0, lane, C);
    __syncthreads();
    stage(W3BP, 128, 0, 64, OFF_W0);                   // grp7
    CP_WAIT(1); __syncthreads();                       // grp6 ready
    gemm_chunk<4>(sA, wb1, 64, r0, n0, lane, C);

    #pragma unroll 1
    for (int h3 = 0; h3 < 2; h3++) {
        // pool the warp's 32-row neighborhood
        const int q2 = (lane & 3) * 2;
        #pragma unroll
        for (int j = 0; j < 8; j++) {
            const int c0 = n0 + j * 8 + q2;
            const float bb0 = bias[256 + h3 * 128 + c0];
            const float bb1 = bias[256 + h3 * 128 + c0 + 1];
            float v0 = fmaxf(fmaxf(C[0][j][0], C[0][j][2]),
                             fmaxf(C[1][j][0], C[1][j][2]));
            float v1 = fmaxf(fmaxf(C[0][j][1], C[0][j][3]),
                             fmaxf(C[1][j][1], C[1][j][3]));
            v0 = fmaxf(v0 + bb0, 0.f);
            v1 = fmaxf(v1 + bb1, 0.f);
            #pragma unroll
            for (int s = 4; s < 32; s <<= 1) {
                v0 = fmaxf(v0, __shfl_xor_sync(0xFFFFFFFFu, v0, s));
                v1 = fmaxf(v1, __shfl_xor_sync(0xFFFFFFFFu, v1, s));
            }
            if (lane < 4) {
                pmax[rg * 128 + c0]     = v0;
                pmax[rg * 128 + c0 + 1] = v1;
            }
        }
        __syncthreads();
        if (h3 == 0) { stage(W3BP, 128, 64, 64, OFF_W1); }   // grp8
        if (tid < 128) {
            const int col = tid;
            float f[8];
            #pragma unroll
            for (int g = 0; g < 8; g++) f[g] = pmax[g * 128 + col];
            const size_t base = ((size_t)(b * 256 + h3 * 128 + col)) * M_ + m0;
            *(float4*)(out + base)     = make_float4(f[0], f[1], f[2], f[3]);
            *(float4*)(out + base + 4) = make_float4(f[4], f[5], f[6], f[7]);
        }
        if (h3 == 0) {
            CP_WAIT(1); __syncthreads();               // grp7 (W3h1 k0-63) ready
            zeroC(C);
            gemm_chunk<4>(sA, wb0, 0, r0, n0, lane, C);
            __syncthreads();
            CP_WAIT(0); __syncthreads();               // grp8 ready
            gemm_chunk<4>(sA, wb1, 64, r0, n0, lane, C);
        }
    }
}

extern "C" void kernel_launch(void* const* d_in, const int* in_sizes, int n_in,
                              void* d_out, int out_size)
{
    const float* xyz  = (const float*)d_in[0];
    const float* feat = (const float*)d_in[1];
    const int*   nbr  = (const int*)d_in[2];
    const int*   anc  = (const int*)d_in[3];
    const float* W1   = (const float*)d_in[4];
    const float* b1   = (const float*)d_in[5];
    const float* W2   = (const float*)d_in[6];
    const float* b2   = (const float*)d_in[7];
    const float* W3   = (const float*)d_in[8];
    const float* b3   = (const float*)d_in[9];
    float* out = (float*)d_out;

    prep_kernel<<<232, 256>>>(W1, W2, W3);
    tr_kernel<<<B_ * (N_ / 64), 256>>>(feat);
    cudaFuncSetAttribute(ps_mma6, cudaFuncAttributeMaxDynamicSharedMemorySize, SMEM_BYTES);
    ps_mma6<<<2048, 512, SMEM_BYTES>>>(xyz, nbr, anc, b1, b2, b3, out);
}

// round 13
// speedup vs baseline: 1.1484x; 1.1484x over previous
#include <cuda_runtime.h>
#include <cuda_bf16.h>
#include <cstdint>
#include <cstddef>

#define B_   8
#define N_   8192
#define M_   2048
#define CIN  64
#define AST  136      // A row stride (bf16 elems) = 272B; ldmatrix rows land conflict-free
#define WST  136      // W row stride (bf16 elems) = 272B

// smem byte offsets (217088 total, 1 CTA/SM)
#define OFF_BIAS 0                       // 512 f32
#define OFF_PMAX 2048                    // 8 x 128 f32
#define OFF_AHI  8192                    // 256 x 136 bf16 = 69632 B
#define OFF_ALO  (OFF_AHI + 69632)
#define OFF_WHI  (OFF_ALO + 69632)       // 128 x 136 bf16 = 34816 B
#define OFF_WLO  (OFF_WHI + 34816)
#define SMEM_BYTES (OFF_WLO + 34816)     // 217088

// 16 MB transposed features: featT[b][n][c]
__device__ float g_featT[(size_t)B_ * N_ * CIN];

__device__ __forceinline__ void bsplit(float v, __nv_bfloat16& h, __nv_bfloat16& l) {
    h = __float2bfloat16(v);
    l = __float2bfloat16(v - __bfloat162float(h));
}
__device__ __forceinline__ uint32_t pk(__nv_bfloat16 a, __nv_bfloat16 b) {
    __nv_bfloat162 t(a, b);
    return *(uint32_t*)&t;
}
// split 4 consecutive cols -> one uint2 to hi, one to lo (elemOff % 4 == 0)
__device__ __forceinline__ void store4q(__nv_bfloat16* hiB, __nv_bfloat16* loB,
                                        int elemOff, const float* v) {
    __nv_bfloat16 h0,l0,h1,l1,h2,l2,h3,l3;
    bsplit(v[0], h0, l0); bsplit(v[1], h1, l1);
    bsplit(v[2], h2, l2); bsplit(v[3], h3, l3);
    uint2 hh; hh.x = pk(h0, h1); hh.y = pk(h2, h3);
    uint2 ll; ll.x = pk(l0, l1); ll.y = pk(l2, l3);
    *(uint2*)(hiB + elemOff) = hh;
    *(uint2*)(loB + elemOff) = ll;
}

__device__ __forceinline__ void mma_bf16(float c[4], const uint32_t a[4],
                                         uint32_t b0, uint32_t b1) {
    asm volatile(
        "mma.sync.aligned.m16n8k16.row.col.f32.bf16.bf16.f32 "
        "{%0,%1,%2,%3}, {%4,%5,%6,%7}, {%8,%9}, {%0,%1,%2,%3};"
        : "+f"(c[0]), "+f"(c[1]), "+f"(c[2]), "+f"(c[3])
        : "r"(a[0]), "r"(a[1]), "r"(a[2]), "r"(a[3]), "r"(b0), "r"(b1));
}
#define LDSM4(d, addr) \
    asm volatile("ldmatrix.sync.aligned.m8n8.x4.shared.b16 {%0,%1,%2,%3}, [%4];" \
        : "=r"((d)[0]), "=r"((d)[1]), "=r"((d)[2]), "=r"((d)[3]) : "r"(addr))

// Warp tile m32 x n64, 3-pass bf16 compensation, ldmatrix operand fetch.
template<int KS>
__device__ __forceinline__ void gemm(const __nv_bfloat16* __restrict__ sAhi,
                                     const __nv_bfloat16* __restrict__ sAlo,
                                     const __nv_bfloat16* __restrict__ sWhi,
                                     const __nv_bfloat16* __restrict__ sWlo,
                                     int r0, int n0, int lane, float C[2][8][4])
{
    #pragma unroll
    for (int mt = 0; mt < 2; mt++)
        #pragma unroll
        for (int j = 0; j < 8; j++)
            #pragma unroll
            for (int x = 0; x < 4; x++) C[mt][j][x] = 0.f;

    // A: lanes 0-15 -> rows 0-15 (k lo 16B); lanes 16-31 -> rows 0-15 (k hi 16B)
    const uint32_t aoff =
        (uint32_t)(((r0 + (lane & 15)) * AST + ((lane >> 4) << 3)) << 1);
    const uint32_t aHi = (uint32_t)__cvta_generic_to_shared(sAhi) + aoff;
    const uint32_t aLo = (uint32_t)__cvta_generic_to_shared(sAlo) + aoff;
    // W: matrices = {j0 klo, j0 khi, j1 klo, j1 khi}; j1 = n+8
    const uint32_t woff =
        (uint32_t)(((n0 + (((lane >> 4) & 1) << 3) + (lane & 7)) * WST
                    + (((lane >> 3) & 1) << 3)) << 1);
    const uint32_t wHi = (uint32_t)__cvta_generic_to_shared(sWhi) + woff;
    const uint32_t wLo = (uint32_t)__cvta_generic_to_shared(sWlo) + woff;

    const uint32_t AMT = 16 * AST * 2;   // bytes between m-tiles
    const uint32_t WP  = 16 * WST * 2;   // bytes between j-pairs

    #pragma unroll 2
    for (int ks = 0; ks < KS; ks++) {
        const uint32_t ko = (uint32_t)(ks * 32);
        uint32_t ah[2][4], al[2][4];
        LDSM4(ah[0], aHi + ko);
        LDSM4(ah[1], aHi + AMT + ko);
        LDSM4(al[0], aLo + ko);
        LDSM4(al[1], aLo + AMT + ko);
        #pragma unroll
        for (int p = 0; p < 4; p++) {
            uint32_t wh[4], wl[4];
            LDSM4(wh, wHi + p * WP + ko);
            LDSM4(wl, wLo + p * WP + ko);
            // j = 2p (regs 0,1) and j = 2p+1 (regs 2,3); per j: hihi, hilo, lohi
            mma_bf16(C[0][2*p],   ah[0], wh[0], wh[1]);
            mma_bf16(C[1][2*p],   ah[1], wh[0], wh[1]);
            mma_bf16(C[0][2*p],   ah[0], wl[0], wl[1]);
            mma_bf16(C[1][2*p],   ah[1], wl[0], wl[1]);
            mma_bf16(C[0][2*p],   al[0], wh[0], wh[1]);
            mma_bf16(C[1][2*p],   al[1], wh[0], wh[1]);
            mma_bf16(C[0][2*p+1], ah[0], wh[2], wh[3]);
            mma_bf16(C[1][2*p+1], ah[1], wh[2], wh[3]);
            mma_bf16(C[0][2*p+1], ah[0], wl[2], wl[3]);
            mma_bf16(C[1][2*p+1], ah[1], wl[2], wl[3]);
            mma_bf16(C[0][2*p+1], al[0], wh[2], wh[3]);
            mma_bf16(C[1][2*p+1], al[1], wh[2], wh[3]);
        }
    }
}

// bias+relu, re-split to bf16 hi/lo, store as next layer's A (caller syncs first)
__device__ __forceinline__ void epi(const float C[2][8][4], const float* __restrict__ bias,
                                    int r0, int n0, int lane,
                                    __nv_bfloat16* __restrict__ sAhi,
                                    __nv_bfloat16* __restrict__ sAlo)
{
    const int rq = lane >> 2, q2 = (lane & 3) * 2;
    #pragma unroll
    for (int mt = 0; mt < 2; mt++) {
        const int ra = r0 + mt * 16 + rq;
        #pragma unroll
        for (int j = 0; j < 8; j++) {
            const int c0 = n0 + j * 8 + q2;
            const float bb0 = bias[c0], bb1 = bias[c0 + 1];
            float v0 = fmaxf(C[mt][j][0] + bb0, 0.f);
            float v1 = fmaxf(C[mt][j][1] + bb1, 0.f);
            float v2 = fmaxf(C[mt][j][2] + bb0, 0.f);
            float v3 = fmaxf(C[mt][j][3] + bb1, 0.f);
            __nv_bfloat16 h, l; __nv_bfloat162 hh, ll;
            bsplit(v0, h, l); hh.x = h; ll.x = l;
            bsplit(v1, h, l); hh.y = h; ll.y = l;
            *(__nv_bfloat162*)(sAhi + ra * AST + c0) = hh;
            *(__nv_bfloat162*)(sAlo + ra * AST + c0) = ll;
            bsplit(v2, h, l); hh.x = h; ll.x = l;
            bsplit(v3, h, l); hh.y = h; ll.y = l;
            *(__nv_bfloat162*)(sAhi + (ra + 8) * AST + c0) = hh;
            *(__nv_bfloat162*)(sAlo + (ra + 8) * AST + c0) = ll;
        }
    }
}

// stage W[k][coloff+n] (lead dim ld) -> [n][k] hi/lo, zero pad k>=kreal
__device__ __forceinline__ void stageW(const float* __restrict__ W, int ld, int coloff,
                                       int kreal, int ktot,
                                       __nv_bfloat16* __restrict__ wHi,
                                       __nv_bfloat16* __restrict__ wLo, int tid)
{
    const int n = tid & 127;
    const int kg = tid >> 7;            // 4 k-groups
    const int kspan = ktot >> 2;        // 20 or 32 (mult of 4)
    #pragma unroll 1
    for (int k0 = kg * kspan; k0 < (kg + 1) * kspan; k0 += 4) {
        float v[4];
        #pragma unroll
        for (int j = 0; j < 4; j++) {
            const int k = k0 + j;
            v[j] = (k < kreal) ? __ldg(W + (size_t)k * ld + coloff + n) : 0.f;
        }
        store4q(wHi, wLo, n * WST + k0, v);
    }
}

// ---------------- feature transpose [C][N] -> [N][C] ----------------
__global__ __launch_bounds__(256) void tr_kernel(const float* __restrict__ feat) {
    __shared__ float t[64][65];
    const int b  = blockIdx.x >> 7;
    const int n0 = (blockIdx.x & 127) << 6;
    const int tid = threadIdx.x;
    const float* fb = feat + (size_t)b * CIN * N_;
    for (int i = tid; i < 64 * 64; i += 256) {
        int c = i >> 6, nj = i & 63;
        t[c][nj] = fb[(size_t)c * N_ + n0 + nj];
    }
    __syncthreads();
    const int nj = tid >> 2, cq = (tid & 3) * 16;
    float* drow = g_featT + ((size_t)b * N_ + n0 + nj) * CIN + cq;
    #pragma unroll
    for (int q = 0; q < 16; q += 4) {
        float4 v = make_float4(t[cq + q][nj], t[cq + q + 1][nj],
                               t[cq + q + 2][nj], t[cq + q + 3][nj]);
        *(float4*)(drow + q) = v;
    }
}

// ---------------- main: 256 rows (8 neighborhoods) per CTA ----------------
__global__ __launch_bounds__(512, 1)
void ps_mma7(const float* __restrict__ xyz, const float* __restrict__ feat,
             const int* __restrict__ nbr, const int* __restrict__ anc,
             const float* __restrict__ W1, const float* __restrict__ b1,
             const float* __restrict__ W2, const float* __restrict__ b2,
             const float* __restrict__ W3, const float* __restrict__ b3,
             float* __restrict__ out)
{
    extern __shared__ char smem[];
    float* bias = (float*)(smem + OFF_BIAS);
    float* pmax = (float*)(smem + OFF_PMAX);
    __nv_bfloat16* sAhi = (__nv_bfloat16*)(smem + OFF_AHI);
    __nv_bfloat16* sAlo = (__nv_bfloat16*)(smem + OFF_ALO);
    __nv_bfloat16* sWhi = (__nv_bfloat16*)(smem + OFF_WHI);
    __nv_bfloat16* sWlo = (__nv_bfloat16*)(smem + OFF_WLO);

    const int tid = threadIdx.x, lane = tid & 31, w = tid >> 5;
    const int ct = blockIdx.x, b = ct >> 8;
    const int m0 = (ct & 255) << 3;        // 8 anchors per CTA

    bias[tid] = (tid < 128) ? b1[tid] : (tid < 256) ? b2[tid - 128] : b3[tid - 256];

    // ---- gather: rows [256][80] = [rel_xyz(3)|feat(64)|0..], 2 threads/row ----
    {
        const int r = tid >> 1, h = tid & 1;
        const int m = m0 + (r >> 5), k = r & 31;
        const int n = nbr[(b * M_ + m) * 32 + k];
        const int a = anc[b * M_ + m];
        const float* xb = xyz + (size_t)b * N_ * 3;
        const float* ft = g_featT + ((size_t)b * N_ + n) * CIN;
        float xr[3];
        if (h == 0) {
            xr[0] = xb[n * 3 + 0] - xb[a * 3 + 0];
            xr[1] = xb[n * 3 + 1] - xb[a * 3 + 1];
            xr[2] = xb[n * 3 + 2] - xb[a * 3 + 2];
        }
        #pragma unroll 1
        for (int cb = h * 4; cb < 80; cb += 8) {
            float v[4];
            #pragma unroll
            for (int j = 0; j < 4; j++) {
                const int c = cb + j;
                v[j] = (c < 3) ? xr[c] : (c < 67) ? __ldg(ft + (c - 3)) : 0.f;
            }
            store4q(sAhi, sAlo, r * AST + cb, v);
        }
    }
    stageW(W1, 128, 0, 67, 80, sWhi, sWlo, tid);
    __syncthreads();

    const int rg = w & 7;               // row group / neighborhood
    const int r0 = rg * 32;
    const int n0 = (w >> 3) * 64;       // col half
    float C[2][8][4];

    // ---- layer 1: [256,80] @ [80,128] ----
    gemm<5>(sAhi, sAlo, sWhi, sWlo, r0, n0, lane, C);
    __syncthreads();
    epi(C, bias, r0, n0, lane, sAhi, sAlo);
    stageW(W2, 128, 0, 128, 128, sWhi, sWlo, tid);
    __syncthreads();

    // ---- layer 2: [256,128] @ [128,128] ----
    gemm<8>(sAhi, sAlo, sWhi, sWlo, r0, n0, lane, C);
    __syncthreads();
    epi(C, bias + 128, r0, n0, lane, sAhi, sAlo);
    stageW(W3, 256, 0, 128, 128, sWhi, sWlo, tid);
    __syncthreads();

    // ---- layer 3 (two 128-col halves) + fused maxpool ----
    #pragma unroll 1
    for (int h3 = 0; h3 < 2; h3++) {
        gemm<8>(sAhi, sAlo, sWhi, sWlo, r0, n0, lane, C);

        const int q2 = (lane & 3) * 2;
        #pragma unroll
        for (int j = 0; j < 8; j++) {
            const int c0 = n0 + j * 8 + q2;     // 0..127 within half
            const float bb0 = bias[256 + h3 * 128 + c0];
            const float bb1 = bias[256 + h3 * 128 + c0 + 1];
            float v0 = fmaxf(fmaxf(C[0][j][0], C[0][j][2]),
                             fmaxf(C[1][j][0], C[1][j][2]));
            float v1 = fmaxf(fmaxf(C[0][j][1], C[0][j][3]),
                             fmaxf(C[1][j][1], C[1][j][3]));
            v0 = fmaxf(v0 + bb0, 0.f);
            v1 = fmaxf(v1 + bb1, 0.f);
            #pragma unroll
            for (int s = 4; s < 32; s <<= 1) {
                v0 = fmaxf(v0, __shfl_xor_sync(0xFFFFFFFFu, v0, s));
                v1 = fmaxf(v1, __shfl_xor_sync(0xFFFFFFFFu, v1, s));
            }
            if (lane < 4) {
                pmax[rg * 128 + c0]     = v0;
                pmax[rg * 128 + c0 + 1] = v1;
            }
        }
        __syncthreads();

        // coalesced out write: 8 consecutive m per col
        if (tid < 128) {
            const int col = tid;
            float f[8];
            #pragma unroll
            for (int g = 0; g < 8; g++) f[g] = pmax[g * 128 + col];
            const size_t base = ((size_t)(b * 256 + h3 * 128 + col)) * M_ + m0;
            *(float4*)(out + base)     = make_float4(f[0], f[1], f[2], f[3]);
            *(float4*)(out + base + 4) = make_float4(f[4], f[5], f[6], f[7]);
        }
        if (h3 == 0)
            stageW(W3, 256, 128, 128, 128, sWhi, sWlo, tid);
        __syncthreads();
    }
}

extern "C" void kernel_launch(void* const* d_in, const int* in_sizes, int n_in,
                              void* d_out, int out_size)
{
    const float* xyz  = (const float*)d_in[0];
    const float* feat = (const float*)d_in[1];
    const int*   nbr  = (const int*)d_in[2];
    const int*   anc  = (const int*)d_in[3];
    const float* W1   = (const float*)d_in[4];
    const float* b1   = (const float*)d_in[5];
    const float* W2   = (const float*)d_in[6];
    const float* b2   = (const float*)d_in[7];
    const float* W3   = (const float*)d_in[8];
    const float* b3   = (const float*)d_in[9];
    float* out = (float*)d_out;

    tr_kernel<<<B_ * (N_ / 64), 256>>>(feat);
    cudaFuncSetAttribute(ps_mma7, cudaFuncAttributeMaxDynamicSharedMemorySize, SMEM_BYTES);
    ps_mma7<<<2048, 512, SMEM_BYTES>>>(xyz, feat, nbr, anc, W1, b1, W2, b2, W3, b3, out);
}

// round 14
// speedup vs baseline: 1.4951x; 1.3020x over previous
#include <cuda_runtime.h>
#include <cuda_fp16.h>
#include <cstdint>
#include <cstddef>

#define B_   8
#define N_   8192
#define M_   2048
#define CIN  64
#define AST  136      // A row stride (fp16 elems) = 272B; ldmatrix rows conflict-free
#define WST  136      // W row stride

// smem byte offsets (182272 total, 1 CTA/SM)
#define OFF_BIAS 0                       // 512 f32
#define OFF_PMAX 2048                    // 8 x 128 f32
#define OFF_AHI  8192                    // 256 x 136 fp16 = 69632 B
#define OFF_ALO  (OFF_AHI + 69632)
#define OFF_WH   (OFF_ALO + 69632)       // 128 x 136 fp16 = 34816 B (hi only)
#define SMEM_BYTES (OFF_WH + 34816)      // 182272

// 16 MB transposed features: featT[b][n][c]
__device__ float g_featT[(size_t)B_ * N_ * CIN];

__device__ __forceinline__ void hsplit(float v, __half& h, __half& l) {
    h = __float2half_rn(v);
    l = __float2half_rn(v - __half2float(h));
}
__device__ __forceinline__ uint32_t pkh(__half a, __half b) {
    __half2 t(a, b);
    return *(uint32_t*)&t;
}
// split 4 consecutive cols -> one uint2 to hi buf, one to lo buf
__device__ __forceinline__ void store4q(__half* hiB, __half* loB,
                                        int elemOff, const float* v) {
    __half h0,l0,h1,l1,h2,l2,h3,l3;
    hsplit(v[0], h0, l0); hsplit(v[1], h1, l1);
    hsplit(v[2], h2, l2); hsplit(v[3], h3, l3);
    uint2 hh; hh.x = pkh(h0, h1); hh.y = pkh(h2, h3);
    uint2 ll; ll.x = pkh(l0, l1); ll.y = pkh(l2, l3);
    *(uint2*)(hiB + elemOff) = hh;
    *(uint2*)(loB + elemOff) = ll;
}
// hi-only variant for weights
__device__ __forceinline__ void store4h(__half* hiB, int elemOff, const float* v) {
    uint2 hh;
    hh.x = pkh(__float2half_rn(v[0]), __float2half_rn(v[1]));
    hh.y = pkh(__float2half_rn(v[2]), __float2half_rn(v[3]));
    *(uint2*)(hiB + elemOff) = hh;
}

__device__ __forceinline__ void mma_f16(float c[4], const uint32_t a[4],
                                        uint32_t b0, uint32_t b1) {
    asm volatile(
        "mma.sync.aligned.m16n8k16.row.col.f32.f16.f16.f32 "
        "{%0,%1,%2,%3}, {%4,%5,%6,%7}, {%8,%9}, {%0,%1,%2,%3};"
        : "+f"(c[0]), "+f"(c[1]), "+f"(c[2]), "+f"(c[3])
        : "r"(a[0]), "r"(a[1]), "r"(a[2]), "r"(a[3]), "r"(b0), "r"(b1));
}
#define LDSM4(d, addr) \
    asm volatile("ldmatrix.sync.aligned.m8n8.x4.shared.b16 {%0,%1,%2,%3}, [%4];" \
        : "=r"((d)[0]), "=r"((d)[1]), "=r"((d)[2]), "=r"((d)[3]) : "r"(addr))

// Warp tile m32 x n64, 2-pass fp16: D = Ahi*Wh + Alo*Wh. ldmatrix fetch.
template<int KS>
__device__ __forceinline__ void gemm(const __half* __restrict__ sAhi,
                                     const __half* __restrict__ sAlo,
                                     const __half* __restrict__ sWh,
                                     int r0, int n0, int lane, float C[2][8][4])
{
    #pragma unroll
    for (int mt = 0; mt < 2; mt++)
        #pragma unroll
        for (int j = 0; j < 8; j++)
            #pragma unroll
            for (int x = 0; x < 4; x++) C[mt][j][x] = 0.f;

    // A: lanes 0-15 -> rows 0-15 (k lo 16B); lanes 16-31 -> rows 0-15 (k hi 16B)
    const uint32_t aoff =
        (uint32_t)(((r0 + (lane & 15)) * AST + ((lane >> 4) << 3)) << 1);
    const uint32_t aHi = (uint32_t)__cvta_generic_to_shared(sAhi) + aoff;
    const uint32_t aLo = (uint32_t)__cvta_generic_to_shared(sAlo) + aoff;
    // W: matrices = {j0 klo, j0 khi, j1 klo, j1 khi}; j1 = n+8
    const uint32_t woff =
        (uint32_t)(((n0 + (((lane >> 4) & 1) << 3) + (lane & 7)) * WST
                    + (((lane >> 3) & 1) << 3)) << 1);
    const uint32_t wH = (uint32_t)__cvta_generic_to_shared(sWh) + woff;

    const uint32_t AMT = 16 * AST * 2;   // bytes between m-tiles
    const uint32_t WP  = 16 * WST * 2;   // bytes between j-pairs

    #pragma unroll 2
    for (int ks = 0; ks < KS; ks++) {
        const uint32_t ko = (uint32_t)(ks * 32);
        uint32_t ah[2][4], al[2][4];
        LDSM4(ah[0], aHi + ko);
        LDSM4(ah[1], aHi + AMT + ko);
        LDSM4(al[0], aLo + ko);
        LDSM4(al[1], aLo + AMT + ko);
        #pragma unroll
        for (int p = 0; p < 4; p++) {
            uint32_t wh[4];
            LDSM4(wh, wH + p * WP + ko);
            // j = 2p (regs 0,1) and j = 2p+1 (regs 2,3); per j: ahi*wh, alo*wh
            mma_f16(C[0][2*p],   ah[0], wh[0], wh[1]);
            mma_f16(C[1][2*p],   ah[1], wh[0], wh[1]);
            mma_f16(C[0][2*p],   al[0], wh[0], wh[1]);
            mma_f16(C[1][2*p],   al[1], wh[0], wh[1]);
            mma_f16(C[0][2*p+1], ah[0], wh[2], wh[3]);
            mma_f16(C[1][2*p+1], ah[1], wh[2], wh[3]);
            mma_f16(C[0][2*p+1], al[0], wh[2], wh[3]);
            mma_f16(C[1][2*p+1], al[1], wh[2], wh[3]);
        }
    }
}

// bias+relu, re-split to fp16 hi/lo, store as next layer's A (caller syncs first)
__device__ __forceinline__ void epi(const float C[2][8][4], const float* __restrict__ bias,
                                    int r0, int n0, int lane,
                                    __half* __restrict__ sAhi,
                                    __half* __restrict__ sAlo)
{
    const int rq = lane >> 2, q2 = (lane & 3) * 2;
    #pragma unroll
    for (int mt = 0; mt < 2; mt++) {
        const int ra = r0 + mt * 16 + rq;
        #pragma unroll
        for (int j = 0; j < 8; j++) {
            const int c0 = n0 + j * 8 + q2;
            const float bb0 = bias[c0], bb1 = bias[c0 + 1];
            float v0 = fmaxf(C[mt][j][0] + bb0, 0.f);
            float v1 = fmaxf(C[mt][j][1] + bb1, 0.f);
            float v2 = fmaxf(C[mt][j][2] + bb0, 0.f);
            float v3 = fmaxf(C[mt][j][3] + bb1, 0.f);
            __half h0,l0,h1,l1;
            uint2 p;
            hsplit(v0, h0, l0); hsplit(v1, h1, l1);
            p.x = pkh(h0, h1); p.y = pkh(l0, l1);
            // pack as {hi01, lo01}? NO - buffers are separate: store hi pair + lo pair
            *(uint32_t*)(sAhi + ra * AST + c0) = p.x;
            *(uint32_t*)(sAlo + ra * AST + c0) = p.y;
            hsplit(v2, h0, l0); hsplit(v3, h1, l1);
            p.x = pkh(h0, h1); p.y = pkh(l0, l1);
            *(uint32_t*)(sAhi + (ra + 8) * AST + c0) = p.x;
            *(uint32_t*)(sAlo + (ra + 8) * AST + c0) = p.y;
        }
    }
}

// stage W[k][coloff+n] (lead dim ld) -> [n][k] fp16 hi, zero pad k>=kreal
__device__ __forceinline__ void stageW(const float* __restrict__ W, int ld, int coloff,
                                       int kreal, int ktot,
                                       __half* __restrict__ wH, int tid)
{
    const int n = tid & 127;
    const int kg = tid >> 7;            // 4 k-groups
    const int kspan = ktot >> 2;        // 20 or 32 (mult of 4)
    #pragma unroll 1
    for (int k0 = kg * kspan; k0 < (kg + 1) * kspan; k0 += 4) {
        float v[4];
        #pragma unroll
        for (int j = 0; j < 4; j++) {
            const int k = k0 + j;
            v[j] = (k < kreal) ? __ldg(W + (size_t)k * ld + coloff + n) : 0.f;
        }
        store4h(wH, n * WST + k0, v);
    }
}

// ---------------- feature transpose [C][N] -> [N][C] ----------------
__global__ __launch_bounds__(256) void tr_kernel(const float* __restrict__ feat) {
    __shared__ float t[64][65];
    const int b  = blockIdx.x >> 7;
    const int n0 = (blockIdx.x & 127) << 6;
    const int tid = threadIdx.x;
    const float* fb = feat + (size_t)b * CIN * N_;
    for (int i = tid; i < 64 * 64; i += 256) {
        int c = i >> 6, nj = i & 63;
        t[c][nj] = fb[(size_t)c * N_ + n0 + nj];
    }
    __syncthreads();
    const int nj = tid >> 2, cq = (tid & 3) * 16;
    float* drow = g_featT + ((size_t)b * N_ + n0 + nj) * CIN + cq;
    #pragma unroll
    for (int q = 0; q < 16; q += 4) {
        float4 v = make_float4(t[cq + q][nj], t[cq + q + 1][nj],
                               t[cq + q + 2][nj], t[cq + q + 3][nj]);
        *(float4*)(drow + q) = v;
    }
}

// ---------------- main: 256 rows (8 neighborhoods) per CTA ----------------
__global__ __launch_bounds__(512, 1)
void ps_mma8(const float* __restrict__ xyz, const float* __restrict__ feat,
             const int* __restrict__ nbr, const int* __restrict__ anc,
             const float* __restrict__ W1, const float* __restrict__ b1,
             const float* __restrict__ W2, const float* __restrict__ b2,
             const float* __restrict__ W3, const float* __restrict__ b3,
             float* __restrict__ out)
{
    extern __shared__ char smem[];
    float* bias = (float*)(smem + OFF_BIAS);
    float* pmax = (float*)(smem + OFF_PMAX);
    __half* sAhi = (__half*)(smem + OFF_AHI);
    __half* sAlo = (__half*)(smem + OFF_ALO);
    __half* sWh  = (__half*)(smem + OFF_WH);

    const int tid = threadIdx.x, lane = tid & 31, w = tid >> 5;
    const int ct = blockIdx.x, b = ct >> 8;
    const int m0 = (ct & 255) << 3;        // 8 anchors per CTA

    bias[tid] = (tid < 128) ? b1[tid] : (tid < 256) ? b2[tid - 128] : b3[tid - 256];

    // ---- gather: rows [256][80] = [rel_xyz(3)|feat(64)|0..], 2 threads/row ----
    {
        const int r = tid >> 1, h = tid & 1;
        const int m = m0 + (r >> 5), k = r & 31;
        const int n = nbr[(b * M_ + m) * 32 + k];
        const int a = anc[b * M_ + m];
        const float* xb = xyz + (size_t)b * N_ * 3;
        const float* ft = g_featT + ((size_t)b * N_ + n) * CIN;
        float xr[3];
        if (h == 0) {
            xr[0] = xb[n * 3 + 0] - xb[a * 3 + 0];
            xr[1] = xb[n * 3 + 1] - xb[a * 3 + 1];
            xr[2] = xb[n * 3 + 2] - xb[a * 3 + 2];
        }
        #pragma unroll 1
        for (int cb = h * 4; cb < 80; cb += 8) {
            float v[4];
            #pragma unroll
            for (int j = 0; j < 4; j++) {
                const int c = cb + j;
                v[j] = (c < 3) ? xr[c] : (c < 67) ? __ldg(ft + (c - 3)) : 0.f;
            }
            store4q(sAhi, sAlo, r * AST + cb, v);
        }
    }
    stageW(W1, 128, 0, 67, 80, sWh, tid);
    __syncthreads();

    const int rg = w & 7;               // row group / neighborhood
    const int r0 = rg * 32;
    const int n0 = (w >> 3) * 64;       // col half
    float C[2][8][4];

    // ---- layer 1: [256,80] @ [80,128] ----
    gemm<5>(sAhi, sAlo, sWh, r0, n0, lane, C);
    __syncthreads();
    epi(C, bias, r0, n0, lane, sAhi, sAlo);
    stageW(W2, 128, 0, 128, 128, sWh, tid);
    __syncthreads();

    // ---- layer 2: [256,128] @ [128,128] ----
    gemm<8>(sAhi, sAlo, sWh, r0, n0, lane, C);
    __syncthreads();
    epi(C, bias + 128, r0, n0, lane, sAhi, sAlo);
    stageW(W3, 256, 0, 128, 128, sWh, tid);
    __syncthreads();

    // ---- layer 3 (two 128-col halves) + fused maxpool ----
    #pragma unroll 1
    for (int h3 = 0; h3 < 2; h3++) {
        gemm<8>(sAhi, sAlo, sWh, r0, n0, lane, C);

        const int q2 = (lane & 3) * 2;
        #pragma unroll
        for (int j = 0; j < 8; j++) {
            const int c0 = n0 + j * 8 + q2;     // 0..127 within half
            const float bb0 = bias[256 + h3 * 128 + c0];
            const float bb1 = bias[256 + h3 * 128 + c0 + 1];
            float v0 = fmaxf(fmaxf(C[0][j][0], C[0][j][2]),
                             fmaxf(C[1][j][0], C[1][j][2]));
            float v1 = fmaxf(fmaxf(C[0][j][1], C[0][j][3]),
                             fmaxf(C[1][j][1], C[1][j][3]));
            v0 = fmaxf(v0 + bb0, 0.f);
            v1 = fmaxf(v1 + bb1, 0.f);
            #pragma unroll
            for (int s = 4; s < 32; s <<= 1) {
                v0 = fmaxf(v0, __shfl_xor_sync(0xFFFFFFFFu, v0, s));
                v1 = fmaxf(v1, __shfl_xor_sync(0xFFFFFFFFu, v1, s));
            }
            if (lane < 4) {
                pmax[rg * 128 + c0]     = v0;
                pmax[rg * 128 + c0 + 1] = v1;
            }
        }
        __syncthreads();

        // coalesced out write: 8 consecutive m per col
        if (tid < 128) {
            const int col = tid;
            float f[8];
            #pragma unroll
            for (int g = 0; g < 8; g++) f[g] = pmax[g * 128 + col];
            const size_t base = ((size_t)(b * 256 + h3 * 128 + col)) * M_ + m0;
            *(float4*)(out + base)     = make_float4(f[0], f[1], f[2], f[3]);
            *(float4*)(out + base + 4) = make_float4(f[4], f[5], f[6], f[7]);
        }
        if (h3 == 0)
            stageW(W3, 256, 128, 128, 128, sWh, tid);
        __syncthreads();
    }
}

extern "C" void kernel_launch(void* const* d_in, const int* in_sizes, int n_in,
                              void* d_out, int out_size)
{
    const float* xyz  = (const float*)d_in[0];
    const float* feat = (const float*)d_in[1];
    const int*   nbr  = (const int*)d_in[2];
    const int*   anc  = (const int*)d_in[3];
    const float* W1   = (const float*)d_in[4];
    const float* b1   = (const float*)d_in[5];
    const float* W2   = (const float*)d_in[6];
    const float* b2   = (const float*)d_in[7];
    const float* W3   = (const float*)d_in[8];
    const float* b3   = (const float*)d_in[9];
    float* out = (float*)d_out;

    tr_kernel<<<B_ * (N_ / 64), 256>>>(feat);
    cudaFuncSetAttribute(ps_mma8, cudaFuncAttributeMaxDynamicSharedMemorySize, SMEM_BYTES);
    ps_mma8<<<2048, 512, SMEM_BYTES>>>(xyz, feat, nbr, anc, W1, b1, W2, b2, W3, b3, out);
}

// round 15
// speedup vs baseline: 2.0139x; 1.3470x over previous
#include <cuda_runtime.h>
#include <cuda_fp16.h>
#include <cstdint>
#include <cstddef>

#define B_   8
#define N_   8192
#define M_   2048
#define CIN  64
#define AST  136      // A row stride (fp16 elems) = 272B; ldmatrix rows conflict-free
#define WST  136      // W row stride

// smem byte offsets (112640 total, 1 CTA/SM)
#define OFF_BIAS 0                       // 512 f32
#define OFF_PMAX 2048                    // 8 x 128 f32
#define OFF_A    8192                    // 256 x 136 fp16 = 69632 B
#define OFF_WH   (OFF_A + 69632)         // 128 x 136 fp16 = 34816 B
#define SMEM_BYTES (OFF_WH + 34816)      // 112640

// 16 MB transposed features: featT[b][n][c]
__device__ float g_featT[(size_t)B_ * N_ * CIN];

__device__ __forceinline__ uint32_t pkh(__half a, __half b) {
    __half2 t(a, b);
    return *(uint32_t*)&t;
}
// round 4 consecutive cols to fp16, one uint2 store
__device__ __forceinline__ void store4h(__half* buf, int elemOff, const float* v) {
    uint2 hh;
    hh.x = pkh(__float2half_rn(v[0]), __float2half_rn(v[1]));
    hh.y = pkh(__float2half_rn(v[2]), __float2half_rn(v[3]));
    *(uint2*)(buf + elemOff) = hh;
}

__device__ __forceinline__ void mma_f16(float c[4], const uint32_t a[4],
                                        uint32_t b0, uint32_t b1) {
    asm volatile(
        "mma.sync.aligned.m16n8k16.row.col.f32.f16.f16.f32 "
        "{%0,%1,%2,%3}, {%4,%5,%6,%7}, {%8,%9}, {%0,%1,%2,%3};"
        : "+f"(c[0]), "+f"(c[1]), "+f"(c[2]), "+f"(c[3])
        : "r"(a[0]), "r"(a[1]), "r"(a[2]), "r"(a[3]), "r"(b0), "r"(b1));
}
#define LDSM4(d, addr) \
    asm volatile("ldmatrix.sync.aligned.m8n8.x4.shared.b16 {%0,%1,%2,%3}, [%4];" \
        : "=r"((d)[0]), "=r"((d)[1]), "=r"((d)[2]), "=r"((d)[3]) : "r"(addr))

// Warp tile m32 x n64, single-pass fp16, ldmatrix fetch.
template<int KS>
__device__ __forceinline__ void gemm(const __half* __restrict__ sA,
                                     const __half* __restrict__ sWh,
                                     int r0, int n0, int lane, float C[2][8][4])
{
    #pragma unroll
    for (int mt = 0; mt < 2; mt++)
        #pragma unroll
        for (int j = 0; j < 8; j++)
            #pragma unroll
            for (int x = 0; x < 4; x++) C[mt][j][x] = 0.f;

    // A: lanes 0-15 -> rows 0-15 (k lo 16B); lanes 16-31 -> rows 0-15 (k hi 16B)
    const uint32_t aoff =
        (uint32_t)(((r0 + (lane & 15)) * AST + ((lane >> 4) << 3)) << 1);
    const uint32_t aP = (uint32_t)__cvta_generic_to_shared(sA) + aoff;
    // W: matrices = {j0 klo, j0 khi, j1 klo, j1 khi}; j1 = n+8
    const uint32_t woff =
        (uint32_t)(((n0 + (((lane >> 4) & 1) << 3) + (lane & 7)) * WST
                    + (((lane >> 3) & 1) << 3)) << 1);
    const uint32_t wP = (uint32_t)__cvta_generic_to_shared(sWh) + woff;

    const uint32_t AMT = 16 * AST * 2;   // bytes between m-tiles
    const uint32_t WP  = 16 * WST * 2;   // bytes between j-pairs

    #pragma unroll 2
    for (int ks = 0; ks < KS; ks++) {
        const uint32_t ko = (uint32_t)(ks * 32);
        uint32_t a0[4], a1[4];
        LDSM4(a0, aP + ko);
        LDSM4(a1, aP + AMT + ko);
        #pragma unroll
        for (int p = 0; p < 4; p++) {
            uint32_t wh[4];
            LDSM4(wh, wP + p * WP + ko);
            mma_f16(C[0][2*p],   a0, wh[0], wh[1]);
            mma_f16(C[1][2*p],   a1, wh[0], wh[1]);
            mma_f16(C[0][2*p+1], a0, wh[2], wh[3]);
            mma_f16(C[1][2*p+1], a1, wh[2], wh[3]);
        }
    }
}

// bias+relu, round to fp16, store as next layer's A (caller syncs first)
__device__ __forceinline__ void epi(const float C[2][8][4], const float* __restrict__ bias,
                                    int r0, int n0, int lane, __half* __restrict__ sA)
{
    const int rq = lane >> 2, q2 = (lane & 3) * 2;
    #pragma unroll
    for (int mt = 0; mt < 2; mt++) {
        const int ra = r0 + mt * 16 + rq;
        #pragma unroll
        for (int j = 0; j < 8; j++) {
            const int c0 = n0 + j * 8 + q2;
            const float bb0 = bias[c0], bb1 = bias[c0 + 1];
            float v0 = fmaxf(C[mt][j][0] + bb0, 0.f);
            float v1 = fmaxf(C[mt][j][1] + bb1, 0.f);
            float v2 = fmaxf(C[mt][j][2] + bb0, 0.f);
            float v3 = fmaxf(C[mt][j][3] + bb1, 0.f);
            *(uint32_t*)(sA + ra * AST + c0) =
                pkh(__float2half_rn(v0), __float2half_rn(v1));
            *(uint32_t*)(sA + (ra + 8) * AST + c0) =
                pkh(__float2half_rn(v2), __float2half_rn(v3));
        }
    }
}

// stage W[k][coloff+n] (lead dim ld) -> [n][k] fp16, zero pad k>=kreal
__device__ __forceinline__ void stageW(const float* __restrict__ W, int ld, int coloff,
                                       int kreal, int ktot,
                                       __half* __restrict__ wH, int tid)
{
    const int n = tid & 127;
    const int kg = tid >> 7;            // 4 k-groups
    const int kspan = ktot >> 2;        // 20 or 32 (mult of 4)
    #pragma unroll 1
    for (int k0 = kg * kspan; k0 < (kg + 1) * kspan; k0 += 4) {
        float v[4];
        #pragma unroll
        for (int j = 0; j < 4; j++) {
            const int k = k0 + j;
            v[j] = (k < kreal) ? __ldg(W + (size_t)k * ld + coloff + n) : 0.f;
        }
        store4h(wH, n * WST + k0, v);
    }
}

// ---------------- feature transpose [C][N] -> [N][C] ----------------
__global__ __launch_bounds__(256) void tr_kernel(const float* __restrict__ feat) {
    __shared__ float t[64][65];
    const int b  = blockIdx.x >> 7;
    const int n0 = (blockIdx.x & 127) << 6;
    const int tid = threadIdx.x;
    const float* fb = feat + (size_t)b * CIN * N_;
    for (int i = tid; i < 64 * 64; i += 256) {
        int c = i >> 6, nj = i & 63;
        t[c][nj] = fb[(size_t)c * N_ + n0 + nj];
    }
    __syncthreads();
    const int nj = tid >> 2, cq = (tid & 3) * 16;
    float* drow = g_featT + ((size_t)b * N_ + n0 + nj) * CIN + cq;
    #pragma unroll
    for (int q = 0; q < 16; q += 4) {
        float4 v = make_float4(t[cq + q][nj], t[cq + q + 1][nj],
                               t[cq + q + 2][nj], t[cq + q + 3][nj]);
        *(float4*)(drow + q) = v;
    }
}

// ---------------- main: 256 rows (8 neighborhoods) per CTA ----------------
__global__ __launch_bounds__(512, 1)
void ps_mma9(const float* __restrict__ xyz, const float* __restrict__ feat,
             const int* __restrict__ nbr, const int* __restrict__ anc,
             const float* __restrict__ W1, const float* __restrict__ b1,
             const float* __restrict__ W2, const float* __restrict__ b2,
             const float* __restrict__ W3, const float* __restrict__ b3,
             float* __restrict__ out)
{
    extern __shared__ char smem[];
    float* bias = (float*)(smem + OFF_BIAS);
    float* pmax = (float*)(smem + OFF_PMAX);
    __half* sA  = (__half*)(smem + OFF_A);
    __half* sWh = (__half*)(smem + OFF_WH);

    const int tid = threadIdx.x, lane = tid & 31, w = tid >> 5;
    const int ct = blockIdx.x, b = ct >> 8;
    const int m0 = (ct & 255) << 3;        // 8 anchors per CTA

    bias[tid] = (tid < 128) ? b1[tid] : (tid < 256) ? b2[tid - 128] : b3[tid - 256];

    // ---- gather: rows [256][80] = [rel_xyz(3)|feat(64)|0..], 2 threads/row ----
    {
        const int r = tid >> 1, h = tid & 1;
        const int m = m0 + (r >> 5), k = r & 31;
        const int n = nbr[(b * M_ + m) * 32 + k];
        const int a = anc[b * M_ + m];
        const float* xb = xyz + (size_t)b * N_ * 3;
        const float* ft = g_featT + ((size_t)b * N_ + n) * CIN;
        float xr[3];
        if (h == 0) {
            xr[0] = xb[n * 3 + 0] - xb[a * 3 + 0];
            xr[1] = xb[n * 3 + 1] - xb[a * 3 + 1];
            xr[2] = xb[n * 3 + 2] - xb[a * 3 + 2];
        }
        #pragma unroll 1
        for (int cb = h * 4; cb < 80; cb += 8) {
            float v[4];
            #pragma unroll
            for (int j = 0; j < 4; j++) {
                const int c = cb + j;
                v[j] = (c < 3) ? xr[c] : (c < 67) ? __ldg(ft + (c - 3)) : 0.f;
            }
            store4h(sA, r * AST + cb, v);
        }
    }
    stageW(W1, 128, 0, 67, 80, sWh, tid);
    __syncthreads();

    const int rg = w & 7;               // row group / neighborhood
    const int r0 = rg * 32;
    const int n0 = (w >> 3) * 64;       // col half
    float C[2][8][4];

    // ---- layer 1: [256,80] @ [80,128] ----
    gemm<5>(sA, sWh, r0, n0, lane, C);
    __syncthreads();
    epi(C, bias, r0, n0, lane, sA);
    stageW(W2, 128, 0, 128, 128, sWh, tid);
    __syncthreads();

    // ---- layer 2: [256,128] @ [128,128] ----
    gemm<8>(sA, sWh, r0, n0, lane, C);
    __syncthreads();
    epi(C, bias + 128, r0, n0, lane, sA);
    stageW(W3, 256, 0, 128, 128, sWh, tid);
    __syncthreads();

    // ---- layer 3 (two 128-col halves) + fused maxpool ----
    #pragma unroll 1
    for (int h3 = 0; h3 < 2; h3++) {
        gemm<8>(sA, sWh, r0, n0, lane, C);

        const int q2 = (lane & 3) * 2;
        #pragma unroll
        for (int j = 0; j < 8; j++) {
            const int c0 = n0 + j * 8 + q2;     // 0..127 within half
            const float bb0 = bias[256 + h3 * 128 + c0];
            const float bb1 = bias[256 + h3 * 128 + c0 + 1];
            float v0 = fmaxf(fmaxf(C[0][j][0], C[0][j][2]),
                             fmaxf(C[1][j][0], C[1][j][2]));
            float v1 = fmaxf(fmaxf(C[0][j][1], C[0][j][3]),
                             fmaxf(C[1][j][1], C[1][j][3]));
            v0 = fmaxf(v0 + bb0, 0.f);
            v1 = fmaxf(v1 + bb1, 0.f);
            #pragma unroll
            for (int s = 4; s < 32; s <<= 1) {
                v0 = fmaxf(v0, __shfl_xor_sync(0xFFFFFFFFu, v0, s));
                v1 = fmaxf(v1, __shfl_xor_sync(0xFFFFFFFFu, v1, s));
            }
            if (lane < 4) {
                pmax[rg * 128 + c0]     = v0;
                pmax[rg * 128 + c0 + 1] = v1;
            }
        }
        __syncthreads();

        // coalesced out write: 8 consecutive m per col
        if (tid < 128) {
            const int col = tid;
            float f[8];
            #pragma unroll
            for (int g = 0; g < 8; g++) f[g] = pmax[g * 128 + col];
            const size_t base = ((size_t)(b * 256 + h3 * 128 + col)) * M_ + m0;
            *(float4*)(out + base)     = make_float4(f[0], f[1], f[2], f[3]);
            *(float4*)(out + base + 4) = make_float4(f[4], f[5], f[6], f[7]);
        }
        if (h3 == 0)
            stageW(W3, 256, 128, 128, 128, sWh, tid);
        __syncthreads();
    }
}

extern "C" void kernel_launch(void* const* d_in, const int* in_sizes, int n_in,
                              void* d_out, int out_size)
{
    const float* xyz  = (const float*)d_in[0];
    const float* feat = (const float*)d_in[1];
    const int*   nbr  = (const int*)d_in[2];
    const int*   anc  = (const int*)d_in[3];
    const float* W1   = (const float*)d_in[4];
    const float* b1   = (const float*)d_in[5];
    const float* W2   = (const float*)d_in[6];
    const float* b2   = (const float*)d_in[7];
    const float* W3   = (const float*)d_in[8];
    const float* b3   = (const float*)d_in[9];
    float* out = (float*)d_out;

    tr_kernel<<<B_ * (N_ / 64), 256>>>(feat);
    cudaFuncSetAttribute(ps_mma9, cudaFuncAttributeMaxDynamicSharedMemorySize, SMEM_BYTES);
    ps_mma9<<<2048, 512, SMEM_BYTES>>>(xyz, feat, nbr, anc, W1, b1, W2, b2, W3, b3, out);
}

// round 17
// speedup vs baseline: 2.9745x; 1.4770x over previous
#include <cuda_runtime.h>
#include <cuda_fp16.h>
#include <cstdint>
#include <cstddef>

#define B_   8
#define N_   8192
#define M_   2048
#define CIN  64
#define AST  136      // A row stride (fp16 elems) = 272B; ldmatrix rows conflict-free
#define WST  136      // W row stride

// smem byte offsets (112640 total, 1 CTA/SM)
#define OFF_BIAS 0                       // 512 f32
#define OFF_PMAX 2048                    // 8 x 128 f32
#define OFF_A    8192                    // 256 x 136 fp16 = 69632 B
#define OFF_WH   (OFF_A + 69632)         // 128 x 136 fp16 = 34816 B
#define SMEM_BYTES (OFF_WH + 34816)      // 112640

// fp16 transposed features: featT[b][n][c]  (8 MB)
__device__ __align__(16) __half g_featTh[(size_t)B_ * N_ * CIN];
// pre-converted fp16 weights in EXACT smem layout: 4 slots x [128 n][136 k]
// slot 0: W1 (X layout [feat64|xyz3|pad]), 1: W2, 2: W3 cols 0-127, 3: W3 cols 128-255
__device__ __align__(16) __half g_wh[4 * 128 * 136];

__device__ __forceinline__ uint32_t pkh(__half a, __half b) {
    __half2 t(a, b);
    return *(uint32_t*)&t;
}

__device__ __forceinline__ void mma_f16(float c[4], const uint32_t a[4],
                                        uint32_t b0, uint32_t b1) {
    asm volatile(
        "mma.sync.aligned.m16n8k16.row.col.f32.f16.f16.f32 "
        "{%0,%1,%2,%3}, {%4,%5,%6,%7}, {%8,%9}, {%0,%1,%2,%3};"
        : "+f"(c[0]), "+f"(c[1]), "+f"(c[2]), "+f"(c[3])
        : "r"(a[0]), "r"(a[1]), "r"(a[2]), "r"(a[3]), "r"(b0), "r"(b1));
}
#define LDSM4(d, addr) \
    asm volatile("ldmatrix.sync.aligned.m8n8.x4.shared.b16 {%0,%1,%2,%3}, [%4];" \
        : "=r"((d)[0]), "=r"((d)[1]), "=r"((d)[2]), "=r"((d)[3]) : "r"(addr))

// Warp tile m32 x n64, single-pass fp16, ldmatrix fetch.
template<int KS>
__device__ __forceinline__ void gemm(const __half* __restrict__ sA,
                                     const __half* __restrict__ sWh,
                                     int r0, int n0, int lane, float C[2][8][4])
{
    #pragma unroll
    for (int mt = 0; mt < 2; mt++)
        #pragma unroll
        for (int j = 0; j < 8; j++)
            #pragma unroll
            for (int x = 0; x < 4; x++) C[mt][j][x] = 0.f;

    const uint32_t aoff =
        (uint32_t)(((r0 + (lane & 15)) * AST + ((lane >> 4) << 3)) << 1);
    const uint32_t aP = (uint32_t)__cvta_generic_to_shared(sA) + aoff;
    const uint32_t woff =
        (uint32_t)(((n0 + (((lane >> 4) & 1) << 3) + (lane & 7)) * WST
                    + (((lane >> 3) & 1) << 3)) << 1);
    const uint32_t wP = (uint32_t)__cvta_generic_to_shared(sWh) + woff;

    const uint32_t AMT = 16 * AST * 2;   // bytes between m-tiles
    const uint32_t WP  = 16 * WST * 2;   // bytes between j-pairs

    #pragma unroll 2
    for (int ks = 0; ks < KS; ks++) {
        const uint32_t ko = (uint32_t)(ks * 32);
        uint32_t a0[4], a1[4];
        LDSM4(a0, aP + ko);
        LDSM4(a1, aP + AMT + ko);
        #pragma unroll
        for (int p = 0; p < 4; p++) {
            uint32_t wh[4];
            LDSM4(wh, wP + p * WP + ko);
            mma_f16(C[0][2*p],   a0, wh[0], wh[1]);
            mma_f16(C[1][2*p],   a1, wh[0], wh[1]);
            mma_f16(C[0][2*p+1], a0, wh[2], wh[3]);
            mma_f16(C[1][2*p+1], a1, wh[2], wh[3]);
        }
    }
}

// bias+relu, round to fp16, store as next layer's A (caller syncs first)
__device__ __forceinline__ void epi(const float C[2][8][4], const float* __restrict__ bias,
                                    int r0, int n0, int lane, __half* __restrict__ sA)
{
    const int rq = lane >> 2, q2 = (lane & 3) * 2;
    #pragma unroll
    for (int mt = 0; mt < 2; mt++) {
        const int ra = r0 + mt * 16 + rq;
        #pragma unroll
        for (int j = 0; j < 8; j++) {
            const int c0 = n0 + j * 8 + q2;
            const float bb0 = bias[c0], bb1 = bias[c0 + 1];
            float v0 = fmaxf(C[mt][j][0] + bb0, 0.f);
            float v1 = fmaxf(C[mt][j][1] + bb1, 0.f);
            float v2 = fmaxf(C[mt][j][2] + bb0, 0.f);
            float v3 = fmaxf(C[mt][j][3] + bb1, 0.f);
            *(uint32_t*)(sA + ra * AST + c0) =
                pkh(__float2half_rn(v0), __float2half_rn(v1));
            *(uint32_t*)(sA + (ra + 8) * AST + c0) =
                pkh(__float2half_rn(v2), __float2half_rn(v3));
        }
    }
}

// copy weight slot (pre-converted, exact layout) into smem: 2176 uint4
// NOTE: ceil(2176/512) = 5 iterations (4 was the R16 bug: rows 120-127 unstaged).
__device__ __forceinline__ void stageW(int slot, __half* __restrict__ sWh, int tid) {
    const uint4* src = (const uint4*)(g_wh + (size_t)slot * 128 * 136);
    uint4* dst = (uint4*)sWh;
    #pragma unroll
    for (int i = 0; i < 5; i++) {
        const int q = tid + i * 512;
        if (q < 2176) dst[q] = __ldg(src + q);
    }
}

// ---------------- prep: convert W1/W2/W3 -> g_wh (fp16, smem layout) ----------------
// X layout: col c<64 -> feat c -> W row (c+3); c in 64..66 -> xyz -> W row (c-64); pad 0.
__global__ __launch_bounds__(256) void prep_kernel(const float* __restrict__ W1,
                                                   const float* __restrict__ W2,
                                                   const float* __restrict__ W3)
{
    const int i = blockIdx.x * 256 + threadIdx.x;   // u32 index
    if (i >= 4 * 128 * 68) return;
    const int s = i / (128 * 68);
    const int rem = i - s * 128 * 68;
    const int n = rem / 68, kp = rem % 68;
    float v[2];
    #pragma unroll
    for (int j = 0; j < 2; j++) {
        const int k = kp * 2 + j;
        float val = 0.f;
        if (s == 0) {
            if (k < 64)      val = W1[(size_t)(k + 3) * 128 + n];
            else if (k < 67) val = W1[(size_t)(k - 64) * 128 + n];
        } else if (s == 1) {
            if (k < 128) val = W2[(size_t)k * 128 + n];
        } else if (s == 2) {
            if (k < 128) val = W3[(size_t)k * 256 + n];
        } else {
            if (k < 128) val = W3[(size_t)k * 256 + 128 + n];
        }
        v[j] = val;
    }
    ((uint32_t*)g_wh)[s * 128 * 68 + n * 68 + kp] =
        pkh(__float2half_rn(v[0]), __float2half_rn(v[1]));
}

// ---------------- feature transpose [C][N] -> [N][C] fp16 ----------------
__global__ __launch_bounds__(256) void tr_kernel(const float* __restrict__ feat) {
    __shared__ float t[64][65];
    const int b  = blockIdx.x >> 7;
    const int n0 = (blockIdx.x & 127) << 6;
    const int tid = threadIdx.x;
    const float* fb = feat + (size_t)b * CIN * N_;
    for (int i = tid; i < 64 * 64; i += 256) {
        int c = i >> 6, nj = i & 63;
        t[c][nj] = fb[(size_t)c * N_ + n0 + nj];
    }
    __syncthreads();
    const int nj = tid >> 2, cq = (tid & 3) * 16;
    uint32_t* drow = (uint32_t*)(g_featTh + ((size_t)b * N_ + n0 + nj) * CIN + cq);
    #pragma unroll
    for (int q = 0; q < 8; q++)
        drow[q] = pkh(__float2half_rn(t[cq + 2*q][nj]),
                      __float2half_rn(t[cq + 2*q + 1][nj]));
}

// ---------------- main: 256 rows (8 neighborhoods) per CTA ----------------
__global__ __launch_bounds__(512, 1)
void ps_mma11(const float* __restrict__ xyz,
              const int* __restrict__ nbr, const int* __restrict__ anc,
              const float* __restrict__ b1, const float* __restrict__ b2,
              const float* __restrict__ b3, float* __restrict__ out)
{
    extern __shared__ char smem[];
    float* bias = (float*)(smem + OFF_BIAS);
    float* pmax = (float*)(smem + OFF_PMAX);
    __half* sA  = (__half*)(smem + OFF_A);
    __half* sWh = (__half*)(smem + OFF_WH);

    const int tid = threadIdx.x, lane = tid & 31, w = tid >> 5;
    const int ct = blockIdx.x, b = ct >> 8;
    const int m0 = (ct & 255) << 3;        // 8 anchors per CTA

    bias[tid] = (tid < 128) ? b1[tid] : (tid < 256) ? b2[tid - 128] : b3[tid - 256];

    // ---- gather: rows [256][80] = [feat(64)|xyz(3)|0..], 2 threads/row ----
    {
        const int r = tid >> 1, h = tid & 1;
        const int m = m0 + (r >> 5), k = r & 31;
        const int n = nbr[(b * M_ + m) * 32 + k];
        const uint4* f4 = (const uint4*)(g_featTh + ((size_t)b * N_ + n) * CIN);
        __half* pA = sA + r * AST;
        if (h == 0) {
            // feats 0..31: 4 x LDG.128 -> 4 x STS.128
            #pragma unroll
            for (int q = 0; q < 4; q++)
                *(uint4*)(pA + q * 8) = __ldg(f4 + q);
        } else {
            // feats 32..63
            #pragma unroll
            for (int q = 0; q < 4; q++)
                *(uint4*)(pA + 32 + q * 8) = __ldg(f4 + 4 + q);
            // xyz -> cols 64..66, zeros 67..79
            const int a = anc[b * M_ + m];
            const float* xb = xyz + (size_t)b * N_ * 3;
            const float x0 = xb[n * 3 + 0] - xb[a * 3 + 0];
            const float x1 = xb[n * 3 + 1] - xb[a * 3 + 1];
            const float x2 = xb[n * 3 + 2] - xb[a * 3 + 2];
            *(uint32_t*)(pA + 64) = pkh(__float2half_rn(x0), __float2half_rn(x1));
            *(uint32_t*)(pA + 66) = pkh(__float2half_rn(x2), __float2half_rn(0.f));
            const uint2 z = make_uint2(0, 0);
            *(uint2*)(pA + 68) = z;
            *(uint2*)(pA + 72) = z;
            *(uint2*)(pA + 76) = z;
        }
    }
    stageW(0, sWh, tid);
    __syncthreads();

    const int rg = w & 7;               // row group / neighborhood
    const int r0 = rg * 32;
    const int n0 = (w >> 3) * 64;       // col half
    float C[2][8][4];

    // ---- layer 1: [256,80] @ [80,128] ----
    gemm<5>(sA, sWh, r0, n0, lane, C);
    __syncthreads();
    epi(C, bias, r0, n0, lane, sA);
    stageW(1, sWh, tid);
    __syncthreads();

    // ---- layer 2: [256,128] @ [128,128] ----
    gemm<8>(sA, sWh, r0, n0, lane, C);
    __syncthreads();
    epi(C, bias + 128, r0, n0, lane, sA);
    stageW(2, sWh, tid);
    __syncthreads();

    // ---- layer 3 (two 128-col halves) + fused maxpool ----
    #pragma unroll 1
    for (int h3 = 0; h3 < 2; h3++) {
        gemm<8>(sA, sWh, r0, n0, lane, C);

        const int q2 = (lane & 3) * 2;
        #pragma unroll
        for (int j = 0; j < 8; j++) {
            const int c0 = n0 + j * 8 + q2;     // 0..127 within half
            const float bb0 = bias[256 + h3 * 128 + c0];
            const float bb1 = bias[256 + h3 * 128 + c0 + 1];
            float v0 = fmaxf(fmaxf(C[0][j][0], C[0][j][2]),
                             fmaxf(C[1][j][0], C[1][j][2]));
            float v1 = fmaxf(fmaxf(C[0][j][1], C[0][j][3]),
                             fmaxf(C[1][j][1], C[1][j][3]));
            v0 = fmaxf(v0 + bb0, 0.f);
            v1 = fmaxf(v1 + bb1, 0.f);
            #pragma unroll
            for (int s = 4; s < 32; s <<= 1) {
                v0 = fmaxf(v0, __shfl_xor_sync(0xFFFFFFFFu, v0, s));
                v1 = fmaxf(v1, __shfl_xor_sync(0xFFFFFFFFu, v1, s));
            }
            if (lane < 4) {
                pmax[rg * 128 + c0]     = v0;
                pmax[rg * 128 + c0 + 1] = v1;
            }
        }
        __syncthreads();

        // coalesced out write: 8 consecutive m per col
        if (tid < 128) {
            const int col = tid;
            float f[8];
            #pragma unroll
            for (int g = 0; g < 8; g++) f[g] = pmax[g * 128 + col];
            const size_t base = ((size_t)(b * 256 + h3 * 128 + col)) * M_ + m0;
            *(float4*)(out + base)     = make_float4(f[0], f[1], f[2], f[3]);
            *(float4*)(out + base + 4) = make_float4(f[4], f[5], f[6], f[7]);
        }
        if (h3 == 0)
            stageW(3, sWh, tid);
        __syncthreads();
    }
}

extern "C" void kernel_launch(void* const* d_in, const int* in_sizes, int n_in,
                              void* d_out, int out_size)
{
    const float* xyz  = (const float*)d_in[0];
    const float* feat = (const float*)d_in[1];
    const int*   nbr  = (const int*)d_in[2];
    const int*   anc  = (const int*)d_in[3];
    const float* W1   = (const float*)d_in[4];
    const float* b1   = (const float*)d_in[5];
    const float* W2   = (const float*)d_in[6];
    const float* b2   = (const float*)d_in[7];
    const float* W3   = (const float*)d_in[8];
    const float* b3   = (const float*)d_in[9];
    float* out = (float*)d_out;

    prep_kernel<<<136, 256>>>(W1, W2, W3);
    tr_kernel<<<B_ * (N_ / 64), 256>>>(feat);
    cudaFuncSetAttribute(ps_mma11, cudaFuncAttributeMaxDynamicSharedMemorySize, SMEM_BYTES);
    ps_mma11<<<2048, 512, SMEM_BYTES>>>(xyz, nbr, anc, b1, b2, b3, out);
}